// round 11
// baseline (speedup 1.0000x reference)
#include <cuda_runtime.h>
#include <cuda_bf16.h>
#include <cstdint>

#define Bn   128
#define Sn   512
#define Ln   64
#define NPAIRS ((Bn-1)*Sn)       // 65024
#define PPB  128
#define NBLK (NPAIRS/PPB)        // 508
#define EPITCH 132               // est column pitch (floats)
#define TPITCH 65                // staging pitch for trans transpose

#define LOG2E 1.4426950408889634f
#define LN2f  0.6931471805599453f

// Zero-initialized at module load; finalizer block resets after use.
__device__ float    g_alpha[Ln];
__device__ double   g_score;
__device__ unsigned g_done;

__device__ __forceinline__ float ex2f(float x){ float y; asm("ex2.approx.f32 %0, %1;" : "=f"(y) : "f"(x)); return y; }
__device__ __forceinline__ float lg2f_(float x){ float y; asm("lg2.approx.f32 %0, %1;" : "=f"(y) : "f"(x)); return y; }
__device__ __forceinline__ void ffma2(unsigned long long& d, unsigned long long a, unsigned long long b){
    asm("fma.rn.f32x2 %0, %1, %2, %0;" : "+l"(d) : "l"(a), "l"(b));
}
__device__ __forceinline__ unsigned long long pack2(float v){
    unsigned long long r; asm("mov.b64 %0, {%1, %1};" : "=l"(r) : "f"(v)); return r;
}

// ---------------------------------------------------------------------------
// Mega kernel (single launch).
// ---------------------------------------------------------------------------
__global__ __launch_bounds__(256, 4) void mega_kernel(
    const float* __restrict__ emit,  const int* __restrict__ labels,
    const int*   __restrict__ mask,  const float* __restrict__ trans,
    const float* __restrict__ strans,const float* __restrict__ etrans,
    float* __restrict__ out)
{
    __shared__ __align__(16) float sT[Ln*Ln];        // plain [j*64 + i] (float4 idx j*16+i4)
    __shared__ __align__(16) float est[Ln*EPITCH];   // [j*132 + p]; front reused as staging
    __shared__ float flags[PPB];
    __shared__ float ssc[8];
    __shared__ int   scnt[4];
    __shared__ unsigned slast;

    int t  = threadIdx.x;
    int bx = blockIdx.x;
    int p0 = bx * PPB;
    float* tmpS = est;                 // staging: tmp[i*65 + j], 64x65 floats

    // ======== front-issue long-latency loads ========
    // trans (4 float4, coalesced)
    float4 tr[4];
    {
        const float4* tr4 = (const float4*)trans;
        #pragma unroll
        for (int it = 0; it < 4; ++it) tr[it] = tr4[t + it*256];
    }
    // emit tile, R7 mapping: p = t>>1, jh = (t&1)*32
    float4 ex[8];
    {
        int p  = t >> 1;
        int jh = (t & 1) * 32;
        const float4* src = (const float4*)(emit + (size_t)(p0 + Sn + p)*Ln + jh);
        #pragma unroll
        for (int q = 0; q < 8; ++q) ex[q] = src[q];
    }
    // scattered score gathers (unconditional; masked at consume)
    int g = -1;
    if (t < PPB)      g = p0 + Sn + t;
    else if (bx < 4)  g = bx*128 + (t - 128);
    int gg = (g >= 0) ? g : 0;
    int l    = labels[gg];
    int lp   = labels[(gg > 0) ? gg - 1 : 0];
    float em_v = emit[(size_t)gg*Ln + l];
    float tr_v = trans[lp*Ln + l];
    int   mk_v = mask[gg];
    int4 mker = make_int4(0,0,0,0);
    if (bx < Bn && t >= 128) mker = ((const int4*)(mask + bx*Sn))[t - 128];

    // ======== stage 1: trans -> tmp[i*65+j] (conflict-free STS) ========
    #pragma unroll
    for (int it = 0; it < 4; ++it){
        int v = t + it*256;            // float4 idx 0..1023
        int i = v >> 4, j4 = (v & 15) * 4;
        float* d = tmpS + i*TPITCH + j4;
        d[0] = tr[it].x; d[1] = tr[it].y; d[2] = tr[it].z; d[3] = tr[it].w;
    }
    __syncthreads();

    // ======== stage 2: tmp -> sT plain layout (2-way LDS, cf STS.128) ========
    #pragma unroll
    for (int it = 0; it < 4; ++it){
        int u = t + it*256;            // 0..1023
        int i4 = u & 15, j = u >> 4;   // j 0..63
        float4 o;
        o.x = ex2f(tmpS[(4*i4  )*TPITCH + j] * LOG2E);
        o.y = ex2f(tmpS[(4*i4+1)*TPITCH + j] * LOG2E);
        o.z = ex2f(tmpS[(4*i4+2)*TPITCH + j] * LOG2E);
        o.w = ex2f(tmpS[(4*i4+3)*TPITCH + j] * LOG2E);
        ((float4*)sT)[j*16 + i4] = o;
    }
    __syncthreads();                   // staging done; est can be overwritten

    // ======== est fill (ex2 + transposed STS, 2-way conflicts) ========
    {
        int p  = t >> 1;
        int jh = (t & 1) * 32;
        #pragma unroll
        for (int q = 0; q < 8; ++q){
            int j = jh + 4*q;
            est[(j  )*EPITCH + p] = ex2f(ex[q].x * LOG2E);
            est[(j+1)*EPITCH + p] = ex2f(ex[q].y * LOG2E);
            est[(j+2)*EPITCH + p] = ex2f(ex[q].z * LOG2E);
            est[(j+3)*EPITCH + p] = ex2f(ex[q].w * LOG2E);
        }
    }
    if (t < PPB) flags[t] = mk_v ? 1.0f : 0.0f;

    // ======== consume score gathers ========
    {
        float v = 0.f;
        if (g >= 0 && mk_v){
            v = em_v;
            if (g & 511) v += tr_v;
        }
        #pragma unroll
        for (int o = 16; o; o >>= 1) v += __shfl_down_sync(0xffffffffu, v, o);
        if ((t & 31) == 0) ssc[t >> 5] = v;
    }
    if (bx < Bn && t >= 128){
        int tt = t - 128;
        int cnt = (mker.x!=0) + (mker.y!=0) + (mker.z!=0) + (mker.w!=0);
        #pragma unroll
        for (int o = 16; o; o >>= 1) cnt += __shfl_down_sync(0xffffffffu, cnt, o);
        if ((tt & 31) == 0) scnt[tt >> 5] = cnt;
    }
    __syncthreads();

    if (t == 0){
        double tot = 0.0;
        #pragma unroll
        for (int i = 0; i < 8; ++i) tot += (double)ssc[i];
        if (bx < Bn){
            int c = scnt[0] + scnt[1] + scnt[2] + scnt[3];
            int end = c - 1; if (end < 0) end = 0;
            const int* lab = labels + bx*Sn;
            tot += (double)strans[lab[0]] + (double)etrans[lab[end]];
        }
        atomicAdd(&g_score, tot);
    }

    // ======== mainloop: packed f32x2 FFMA, linear addressing ========
    const int i4 = t & 15;
    const int pg = t >> 4;
    unsigned long long acc[4][4];
    #pragma unroll
    for (int k = 0; k < 4; ++k)
        #pragma unroll
        for (int m = 0; m < 4; ++m) acc[k][m] = 0ull;

    const float4*     sT4 = (const float4*)sT;
    const ulonglong2* pE  = (const ulonglong2*)(est) + pg*2;   // step 33/j

    #pragma unroll 8
    for (int j = 0; j < 64; ++j){
        float4 tv = sT4[j*16 + i4];
        ulonglong2 ea = pE[j*33];
        ulonglong2 eb = pE[j*33 + 1];
        unsigned long long tp[4] = {pack2(tv.x), pack2(tv.y), pack2(tv.z), pack2(tv.w)};
        unsigned long long ep[4] = {ea.x, ea.y, eb.x, eb.y};
        #pragma unroll
        for (int k = 0; k < 4; ++k){
            ffma2(acc[k][0], tp[k], ep[0]);
            ffma2(acc[k][1], tp[k], ep[1]);
            ffma2(acc[k][2], tp[k], ep[2]);
            ffma2(acc[k][3], tp[k], ep[3]);
        }
    }

    // ======== unpack + log2 + masked accumulate ========
    float csum[4] = {0.f, 0.f, 0.f, 0.f};
    #pragma unroll
    for (int m = 0; m < 4; ++m){
        float f0 = flags[(pg << 3) + 2*m];
        float f1 = flags[(pg << 3) + 2*m + 1];
        #pragma unroll
        for (int k = 0; k < 4; ++k){
            float lo = __uint_as_float((unsigned)(acc[k][m] & 0xffffffffull));
            float hi = __uint_as_float((unsigned)(acc[k][m] >> 32));
            csum[k] += f0 * lg2f_(lo) + f1 * lg2f_(hi);
        }
    }

    __syncthreads();
    float* red = est;                  // reuse est
    #pragma unroll
    for (int k = 0; k < 4; ++k) red[pg*64 + (i4 << 2) + k] = csum[k];
    __syncthreads();

    if (t < Ln){
        float s = 0.f;
        #pragma unroll
        for (int gi = 0; gi < 16; ++gi) s += red[gi*64 + t];
        atomicAdd(&g_alpha[t], s * LN2f);
    }

    // ======== last-block finalize + state reset ========
    __threadfence();
    if (t == 0){
        unsigned prev = atomicAdd(&g_done, 1u);
        slast = (prev == NBLK - 1) ? 1u : 0u;
    }
    __syncthreads();
    if (slast){
        float a = -1e30f;
        if (t < Ln) a = g_alpha[t] + emit[t];          // + emit[0,0,:]
        float m = a;
        #pragma unroll
        for (int o = 16; o; o >>= 1) m = fmaxf(m, __shfl_xor_sync(0xffffffffu, m, o));
        if ((t & 31) == 0) red[t >> 5] = m;
        __syncthreads();
        m = red[0];
        #pragma unroll
        for (int i = 1; i < 8; ++i) m = fmaxf(m, red[i]);
        float e = (t < Ln) ? ex2f((a - m) * LOG2E) : 0.f;
        #pragma unroll
        for (int o = 16; o; o >>= 1) e += __shfl_xor_sync(0xffffffffu, e, o);
        if ((t & 31) == 0) red[8 + (t >> 5)] = e;
        __syncthreads();
        if (t == 0){
            float es = 0.f;
            #pragma unroll
            for (int i = 0; i < 8; ++i) es += red[8 + i];
            double logZ = (double)m + (double)(LN2f * lg2f_(es));
            out[0] = (float)((logZ - g_score) / (double)Bn);
        }
        __syncthreads();
        if (t < Ln)  g_alpha[t] = 0.0f;
        if (t == 0){ g_score = 0.0; g_done = 0u; }
    }
}

// ---------------------------------------------------------------------------
extern "C" void kernel_launch(void* const* d_in, const int* in_sizes, int n_in,
                              void* d_out, int out_size)
{
    const float* emit   = (const float*)d_in[0];
    const int*   labels = (const int*)d_in[1];
    const int*   mask   = (const int*)d_in[2];
    const float* trans  = (const float*)d_in[3];
    const float* strans = (const float*)d_in[4];
    const float* etrans = (const float*)d_in[5];
    float* out = (float*)d_out;

    mega_kernel<<<NBLK, 256>>>(emit, labels, mask, trans, strans, etrans, out);
}

// round 12
// speedup vs baseline: 1.0855x; 1.0855x over previous
#include <cuda_runtime.h>
#include <cuda_bf16.h>
#include <cstdint>

#define Bn   128
#define Sn   512
#define Ln   64
#define NPAIRS ((Bn-1)*Sn)       // 65024
#define PPB2 256                 // pairs per block (2 tiles of 128)
#define NBLK2 (NPAIRS/PPB2)      // 254
#define EPITCH 132               // est column pitch (floats)
#define TP 68                    // sT pitch in floats (17 float4)

#define LOG2E 1.4426950408889634f
#define LN2f  0.6931471805599453f

// Zero-initialized at module load; finalizer block resets after use.
__device__ float    g_alpha[Ln];
__device__ double   g_score;
__device__ unsigned g_done;

__device__ __forceinline__ float ex2f(float x){ float y; asm("ex2.approx.f32 %0, %1;" : "=f"(y) : "f"(x)); return y; }
__device__ __forceinline__ float lg2f_(float x){ float y; asm("lg2.approx.f32 %0, %1;" : "=f"(y) : "f"(x)); return y; }
__device__ __forceinline__ void ffma2(unsigned long long& d, unsigned long long a, unsigned long long b){
    asm("fma.rn.f32x2 %0, %1, %2, %0;" : "+l"(d) : "l"(a), "l"(b));
}
__device__ __forceinline__ unsigned long long pack2(float v){
    unsigned long long r; asm("mov.b64 %0, {%1, %1};" : "=l"(r) : "f"(v)); return r;
}

// One 128-pair tile mainloop + epilogue; accumulates masked log2 sums into csum.
__device__ __forceinline__ void tile_main(const float* __restrict__ sT,
                                          const float* __restrict__ est,
                                          const float* __restrict__ flags,
                                          int t, float csum[4])
{
    const int i4 = t & 15;
    const int pg = t >> 4;
    unsigned long long acc[4][4];
    #pragma unroll
    for (int k = 0; k < 4; ++k)
        #pragma unroll
        for (int m = 0; m < 4; ++m) acc[k][m] = 0ull;

    const float4*     sT4 = (const float4*)sT;                 // [j*17 + i4]
    const ulonglong2* pE  = (const ulonglong2*)(est) + pg*2;   // step 33/j

    #pragma unroll 8
    for (int j = 0; j < 64; ++j){
        float4 tv = sT4[j*17 + i4];
        ulonglong2 ea = pE[j*33];
        ulonglong2 eb = pE[j*33 + 1];
        unsigned long long tp[4] = {pack2(tv.x), pack2(tv.y), pack2(tv.z), pack2(tv.w)};
        unsigned long long ep[4] = {ea.x, ea.y, eb.x, eb.y};
        #pragma unroll
        for (int k = 0; k < 4; ++k){
            ffma2(acc[k][0], tp[k], ep[0]);
            ffma2(acc[k][1], tp[k], ep[1]);
            ffma2(acc[k][2], tp[k], ep[2]);
            ffma2(acc[k][3], tp[k], ep[3]);
        }
    }
    #pragma unroll
    for (int m = 0; m < 4; ++m){
        float f0 = flags[(pg << 3) + 2*m];
        float f1 = flags[(pg << 3) + 2*m + 1];
        #pragma unroll
        for (int k = 0; k < 4; ++k){
            float lo = __uint_as_float((unsigned)(acc[k][m] & 0xffffffffull));
            float hi = __uint_as_float((unsigned)(acc[k][m] >> 32));
            csum[k] += f0 * lg2f_(lo) + f1 * lg2f_(hi);
        }
    }
}

// ---------------------------------------------------------------------------
// Mega kernel (single launch).  254 blocks x 256 pairs (two 128-pair tiles).
// ---------------------------------------------------------------------------
__global__ __launch_bounds__(256, 4) void mega_kernel(
    const float* __restrict__ emit,  const int* __restrict__ labels,
    const int*   __restrict__ mask,  const float* __restrict__ trans,
    const float* __restrict__ strans,const float* __restrict__ etrans,
    float* __restrict__ out)
{
    __shared__ __align__(16) float sT[Ln*TP];        // padded [j*68 + i]
    __shared__ __align__(16) float est[Ln*EPITCH];   // [j*132 + p]
    __shared__ float flags[128];
    __shared__ float ssc[8];
    __shared__ int   scnt[4];
    __shared__ unsigned slast;

    int t  = threadIdx.x;
    int bx = blockIdx.x;
    int p0 = bx * PPB2;                // pairs p0 .. p0+255

    // ======== front-issue long-latency loads ========
    // emit tile 0 (lane-linear float4)
    float4 ex[8];
    const float4* e4 = (const float4*)(emit + (size_t)(p0 + Sn)*Ln);
    #pragma unroll
    for (int it = 0; it < 8; ++it) ex[it] = e4[t + it*256];
    // per-pair score gather (pair index p0+t; mask idx = p0+512+t)
    int g = p0 + Sn + t;
    int l    = labels[g];
    int lp   = labels[g - 1];
    float em_v = emit[(size_t)g*Ln + l];
    float tr_v = trans[lp*Ln + l];
    int   mk_v = mask[g];
    // b=0 region gathers (blocks 0,1 only)
    float v0 = 0.f;
    if (bx < 2){
        int g2 = bx*256 + t;                // 0..511
        int l2 = labels[g2];
        int g2m = (g2 > 0) ? g2 - 1 : 0;
        float e2v = emit[(size_t)g2*Ln + l2];
        float t2v = trans[labels[g2m]*Ln + l2];
        if (mask[g2]){ v0 = e2v; if (g2 & 511) v0 += t2v; }
    }
    int4 mker = make_int4(0,0,0,0);
    if (bx < Bn && t >= 128) mker = ((const int4*)(mask + bx*Sn))[t - 128];

    // ======== sT build: coalesced trans LDG -> ex2 -> padded STS (once) ========
    #pragma unroll
    for (int it = 0; it < 16; ++it){
        int o = t + it*256;            // 0..4095
        int i = o >> 6, j = o & 63;    // consecutive lanes -> consecutive j (coalesced)
        sT[j*TP + i] = ex2f(trans[i*64 + j] * LOG2E);
    }
    // ======== est fill tile 0 (from hoisted regs) ========
    #pragma unroll
    for (int it = 0; it < 8; ++it){
        int v = t + it*256;
        int p  = v >> 4;
        int j0 = (v & 15) * 4;
        est[(j0  )*EPITCH + p] = ex2f(ex[it].x * LOG2E);
        est[(j0+1)*EPITCH + p] = ex2f(ex[it].y * LOG2E);
        est[(j0+2)*EPITCH + p] = ex2f(ex[it].z * LOG2E);
        est[(j0+3)*EPITCH + p] = ex2f(ex[it].w * LOG2E);
    }
    if (t < 128) flags[t] = mk_v ? 1.0f : 0.0f;   // mask[p0+512+t], t<128 = tile-0 pairs

    // ======== consume score gathers ========
    {
        float v = v0;
        if (mk_v){
            v += em_v;
            if ((p0 + t) & 511) v += tr_v;         // s != 0
        }
        #pragma unroll
        for (int o = 16; o; o >>= 1) v += __shfl_down_sync(0xffffffffu, v, o);
        if ((t & 31) == 0) ssc[t >> 5] = v;
    }
    if (bx < Bn && t >= 128){
        int tt = t - 128;
        int cnt = (mker.x!=0) + (mker.y!=0) + (mker.z!=0) + (mker.w!=0);
        #pragma unroll
        for (int o = 16; o; o >>= 1) cnt += __shfl_down_sync(0xffffffffu, cnt, o);
        if ((tt & 31) == 0) scnt[tt >> 5] = cnt;
    }
    __syncthreads();

    if (t == 0){
        double tot = 0.0;
        #pragma unroll
        for (int i = 0; i < 8; ++i) tot += (double)ssc[i];
        if (bx < Bn){
            int c = scnt[0] + scnt[1] + scnt[2] + scnt[3];
            int end = c - 1; if (end < 0) end = 0;
            const int* lab = labels + bx*Sn;
            tot += (double)strans[lab[0]] + (double)etrans[lab[end]];
        }
        atomicAdd(&g_score, tot);
    }

    // ======== tile 0 mainloop ========
    float csum[4] = {0.f, 0.f, 0.f, 0.f};
    tile_main(sT, est, flags, t, csum);

    // ======== tile 1: refill est + flags, run again ========
    __syncthreads();                   // everyone done reading est (tile 0)
    {
        const float4* e4b = e4 + 2048; // +128 rows * 16 float4
        #pragma unroll
        for (int it = 0; it < 8; ++it){
            int v = t + it*256;
            float4 x = e4b[v];
            int p  = v >> 4;
            int j0 = (v & 15) * 4;
            est[(j0  )*EPITCH + p] = ex2f(x.x * LOG2E);
            est[(j0+1)*EPITCH + p] = ex2f(x.y * LOG2E);
            est[(j0+2)*EPITCH + p] = ex2f(x.z * LOG2E);
            est[(j0+3)*EPITCH + p] = ex2f(x.w * LOG2E);
        }
        if (t < 128) flags[t] = mask[p0 + Sn + 128 + t] ? 1.0f : 0.0f;
    }
    __syncthreads();
    tile_main(sT, est, flags, t, csum);

    // ======== block reduction ========
    __syncthreads();
    float* red = est;                  // reuse est
    const int i4 = t & 15, pg = t >> 4;
    #pragma unroll
    for (int k = 0; k < 4; ++k) red[pg*64 + (i4 << 2) + k] = csum[k];
    __syncthreads();

    if (t < Ln){
        float s = 0.f;
        #pragma unroll
        for (int gi = 0; gi < 16; ++gi) s += red[gi*64 + t];
        atomicAdd(&g_alpha[t], s * LN2f);
    }

    // ======== last-block finalize + state reset ========
    __threadfence();
    if (t == 0){
        unsigned prev = atomicAdd(&g_done, 1u);
        slast = (prev == NBLK2 - 1) ? 1u : 0u;
    }
    __syncthreads();
    if (slast){
        float a = -1e30f;
        if (t < Ln) a = g_alpha[t] + emit[t];          // + emit[0,0,:]
        float m = a;
        #pragma unroll
        for (int o = 16; o; o >>= 1) m = fmaxf(m, __shfl_xor_sync(0xffffffffu, m, o));
        if ((t & 31) == 0) red[t >> 5] = m;
        __syncthreads();
        m = red[0];
        #pragma unroll
        for (int i = 1; i < 8; ++i) m = fmaxf(m, red[i]);
        float e = (t < Ln) ? ex2f((a - m) * LOG2E) : 0.f;
        #pragma unroll
        for (int o = 16; o; o >>= 1) e += __shfl_xor_sync(0xffffffffu, e, o);
        if ((t & 31) == 0) red[8 + (t >> 5)] = e;
        __syncthreads();
        if (t == 0){
            float es = 0.f;
            #pragma unroll
            for (int i = 0; i < 8; ++i) es += red[8 + i];
            double logZ = (double)m + (double)(LN2f * lg2f_(es));
            out[0] = (float)((logZ - g_score) / (double)Bn);
        }
        __syncthreads();
        if (t < Ln)  g_alpha[t] = 0.0f;
        if (t == 0){ g_score = 0.0; g_done = 0u; }
    }
}

// ---------------------------------------------------------------------------
extern "C" void kernel_launch(void* const* d_in, const int* in_sizes, int n_in,
                              void* d_out, int out_size)
{
    const float* emit   = (const float*)d_in[0];
    const int*   labels = (const int*)d_in[1];
    const int*   mask   = (const int*)d_in[2];
    const float* trans  = (const float*)d_in[3];
    const float* strans = (const float*)d_in[4];
    const float* etrans = (const float*)d_in[5];
    float* out = (float*)d_out;

    mega_kernel<<<NBLK2, 256>>>(emit, labels, mask, trans, strans, etrans, out);
}